// round 1
// baseline (speedup 1.0000x reference)
#include <cuda_runtime.h>
#include <math.h>

#define B_SZ   32
#define CH     256
#define L_SEQ  784
#define DI     512
#define DS     16
#define DCONV  4
#define DTR    16
#define MTOT   (B_SZ * L_SEQ)   // 25088

// ---------------- scratch (static __device__, no allocation) ----------------
__device__ float g_xn  [(size_t)MTOT * CH];        // layernormed, (B*L, C)
__device__ float g_xz  [(size_t)MTOT * 2 * DI];    // in_proj out, (B*L, 1024)
__device__ float g_xc  [(size_t)MTOT * DI];        // conv+silu out
__device__ float g_xdbl[(size_t)MTOT * 48];        // x_proj out (dt_r | B | C)
__device__ float g_dt  [(size_t)MTOT * DI];        // softplus(dt)
__device__ float g_y   [(size_t)MTOT * DI];        // scan output (gated)
__device__ float g_xbuf[(size_t)B_SZ * CH * L_SEQ];// inter-depth activations (B,C,L)

// ---------------- LayerNorm over channels, with (B,C,L) -> (B*L, C) ----------
__global__ void ln_kernel(const float* __restrict__ x,
                          const float* __restrict__ w,
                          const float* __restrict__ bb,
                          float* __restrict__ out) {
    int bl = blockIdx.x;                  // b*L + l
    int b  = bl / L_SEQ, l = bl % L_SEQ;
    int c  = threadIdx.x;                 // 256 threads = channels
    float v = x[((size_t)b * CH + c) * L_SEQ + l];

    __shared__ float s1[8], s2[8];
    float a = v, q = v * v;
    #pragma unroll
    for (int o = 16; o > 0; o >>= 1) {
        a += __shfl_xor_sync(0xffffffffu, a, o);
        q += __shfl_xor_sync(0xffffffffu, q, o);
    }
    int wid = c >> 5;
    if ((c & 31) == 0) { s1[wid] = a; s2[wid] = q; }
    __syncthreads();
    if (c < 8) {
        a = s1[c]; q = s2[c];
        #pragma unroll
        for (int o = 4; o > 0; o >>= 1) {
            a += __shfl_xor_sync(0x000000ffu, a, o);
            q += __shfl_xor_sync(0x000000ffu, q, o);
        }
        if (c == 0) { s1[0] = a; s2[0] = q; }
    }
    __syncthreads();
    float mu  = s1[0] * (1.0f / CH);
    float var = s2[0] * (1.0f / CH) - mu * mu;
    float inv = rsqrtf(var + 1e-5f);
    out[(size_t)bl * CH + c] = (v - mu) * inv * w[c] + bb[c];
}

// ---------------- generic GEMM: C[M,N] = A[M,K] * B[N,K]^T --------------------
// BM=BN=64, BK=16, 256 threads, 4x4 per thread. transOut writes (B,N,L) layout.
__global__ void gemm_nt(const float* __restrict__ A, const float* __restrict__ Bw,
                        float* __restrict__ C, int M, int N, int K, int transOut) {
    __shared__ float As[16][64];
    __shared__ float Bs[16][64];
    int bm = blockIdx.y * 64, bn = blockIdx.x * 64;
    int tid = threadIdx.x;
    int tx = tid & 15, ty = tid >> 4;       // 16x16 thread grid
    int lr = tid >> 2, lc = tid & 3;        // loader: row 0..63, float4 col 0..3

    float acc[4][4];
    #pragma unroll
    for (int i = 0; i < 4; i++)
        #pragma unroll
        for (int j = 0; j < 4; j++) acc[i][j] = 0.0f;

    for (int k0 = 0; k0 < K; k0 += 16) {
        float4 va = make_float4(0.f, 0.f, 0.f, 0.f);
        float4 vb = make_float4(0.f, 0.f, 0.f, 0.f);
        int ra = bm + lr;
        if (ra < M) va = *reinterpret_cast<const float4*>(A + (size_t)ra * K + k0 + lc * 4);
        int rb = bn + lr;
        if (rb < N) vb = *reinterpret_cast<const float4*>(Bw + (size_t)rb * K + k0 + lc * 4);

        As[lc*4+0][lr] = va.x; As[lc*4+1][lr] = va.y;
        As[lc*4+2][lr] = va.z; As[lc*4+3][lr] = va.w;
        Bs[lc*4+0][lr] = vb.x; Bs[lc*4+1][lr] = vb.y;
        Bs[lc*4+2][lr] = vb.z; Bs[lc*4+3][lr] = vb.w;
        __syncthreads();

        #pragma unroll
        for (int k = 0; k < 16; k++) {
            float4 a4 = *reinterpret_cast<const float4*>(&As[k][ty * 4]);
            float4 b4 = *reinterpret_cast<const float4*>(&Bs[k][tx * 4]);
            float ar[4] = {a4.x, a4.y, a4.z, a4.w};
            float br[4] = {b4.x, b4.y, b4.z, b4.w};
            #pragma unroll
            for (int i = 0; i < 4; i++)
                #pragma unroll
                for (int j = 0; j < 4; j++)
                    acc[i][j] = fmaf(ar[i], br[j], acc[i][j]);
        }
        __syncthreads();
    }

    #pragma unroll
    for (int i = 0; i < 4; i++) {
        int row = bm + ty * 4 + i;
        if (row >= M) continue;
        #pragma unroll
        for (int j = 0; j < 4; j++) {
            int col = bn + tx * 4 + j;
            if (col >= N) continue;
            if (transOut) {
                int b = row / L_SEQ, l = row % L_SEQ;
                C[((size_t)b * N + col) * L_SEQ + l] = acc[i][j];
            } else {
                C[(size_t)row * N + col] = acc[i][j];
            }
        }
    }
}

// ---------------- causal depthwise conv (k=4) + SiLU --------------------------
__global__ void conv_silu_kernel(const float* __restrict__ cw,
                                 const float* __restrict__ cb) {
    int idx = blockIdx.x * 256 + threadIdx.x;   // over MTOT*DI (exact multiple)
    int d  = idx & (DI - 1);
    int bl = idx >> 9;
    int l  = bl % L_SEQ;
    float acc = cb[d];
    #pragma unroll
    for (int k = 0; k < DCONV; k++) {
        int ll = l - 3 + k;
        if (ll >= 0)
            acc = fmaf(g_xz[(size_t)(bl - 3 + k) * (2 * DI) + d], cw[d * DCONV + k], acc);
    }
    acc = acc / (1.0f + __expf(-acc));          // silu
    g_xc[(size_t)idx] = acc;
}

// ---------------- dt = softplus(dt_r @ W^T + b) --------------------------------
__global__ void dtproj_kernel(const float* __restrict__ dtw,
                              const float* __restrict__ dtb) {
    int blk = blockIdx.x;                       // 2 blocks per (b,l)
    int bl  = blk >> 1;
    int d   = ((blk & 1) << 8) + threadIdx.x;
    __shared__ float r[DTR];
    if (threadIdx.x < DTR) r[threadIdx.x] = g_xdbl[(size_t)bl * 48 + threadIdx.x];
    __syncthreads();
    float acc = dtb[d];
    #pragma unroll
    for (int i = 0; i < DTR; i++) acc = fmaf(r[i], dtw[d * DTR + i], acc);
    acc = (acc > 20.0f) ? acc : log1pf(__expf(acc));   // softplus
    g_dt[(size_t)bl * DI + d] = acc;
}

// ---------------- selective scan, 2 threads per (b,d), 8 states each ----------
__global__ void scan_kernel(const float* __restrict__ A_log,
                            const float* __restrict__ Dp) {
    int b    = blockIdx.x;
    int tid  = threadIdx.x;
    int dl   = tid >> 1, half = tid & 1;
    int d    = blockIdx.y * 128 + dl;

    float a[8];
    #pragma unroll
    for (int s = 0; s < 8; s++) a[s] = -__expf(A_log[d * DS + half * 8 + s]);
    float Dd = Dp[d];

    float h[8];
    #pragma unroll
    for (int s = 0; s < 8; s++) h[s] = 0.0f;

    __shared__ float sBC[16][32];   // per-step B(16) | C(16)

    for (int c0 = 0; c0 < L_SEQ; c0 += 16) {
        __syncthreads();
        for (int i = tid; i < 16 * 32; i += 256) {
            int st = i >> 5, j = i & 31;
            sBC[st][j] = g_xdbl[((size_t)b * L_SEQ + c0 + st) * 48 + 16 + j];
        }
        __syncthreads();
        #pragma unroll 4
        for (int st = 0; st < 16; st++) {
            size_t row = (size_t)b * L_SEQ + c0 + st;
            float dtv = g_dt[row * DI + d];
            float xv  = g_xc[row * DI + d];
            float dtx = dtv * xv;
            float yacc = 0.0f;
            #pragma unroll
            for (int s = 0; s < 8; s++) {
                float dA = __expf(dtv * a[s]);
                h[s] = fmaf(h[s], dA, dtx * sBC[st][half * 8 + s]);
                yacc = fmaf(h[s], sBC[st][16 + half * 8 + s], yacc);
            }
            yacc += __shfl_xor_sync(0xffffffffu, yacc, 1);
            if (half == 0) {
                float zv = g_xz[row * 2 * DI + DI + d];
                float yf = fmaf(xv, Dd, yacc) * (zv / (1.0f + __expf(-zv)));
                g_y[row * DI + d] = yf;
            }
        }
    }
}

// ------------------------------- launcher -------------------------------------
extern "C" void kernel_launch(void* const* d_in, const int* in_sizes, int n_in,
                              void* d_out, int out_size) {
    const float* bbox   = (const float*)d_in[0];
    const float* norm_w = (const float*)d_in[1];
    const float* norm_b = (const float*)d_in[2];
    const float* in_w   = (const float*)d_in[3];
    const float* conv_w = (const float*)d_in[4];
    const float* conv_b = (const float*)d_in[5];
    const float* xp_w   = (const float*)d_in[6];
    const float* dtp_w  = (const float*)d_in[7];
    const float* dtp_b  = (const float*)d_in[8];
    const float* A_log  = (const float*)d_in[9];
    const float* Dp     = (const float*)d_in[10];
    const float* out_w  = (const float*)d_in[11];
    float* out = (float*)d_out;

    float *xn, *xz, *xc, *xdbl, *yy, *xbuf;
    cudaGetSymbolAddress((void**)&xn,   g_xn);
    cudaGetSymbolAddress((void**)&xz,   g_xz);
    cudaGetSymbolAddress((void**)&xc,   g_xc);
    cudaGetSymbolAddress((void**)&xdbl, g_xdbl);
    cudaGetSymbolAddress((void**)&yy,   g_y);
    cudaGetSymbolAddress((void**)&xbuf, g_xbuf);

    for (int i = 0; i < 2; i++) {
        const float* xin = (i == 0) ? bbox : xbuf;
        float* xout      = (i == 0) ? xbuf : out;

        // 1) layernorm + layout change (B,C,L) -> (B*L,C)
        ln_kernel<<<MTOT, 256>>>(xin, norm_w + i * CH, norm_b + i * CH, xn);

        // 2) in_proj: (B*L,256) x (1024,256)^T -> (B*L,1024)
        {
            dim3 g(2 * DI / 64, MTOT / 64);
            gemm_nt<<<g, 256>>>(xn, in_w + (size_t)i * 2 * DI * CH, xz,
                                MTOT, 2 * DI, CH, 0);
        }

        // 3) causal conv + silu -> xc
        conv_silu_kernel<<<(MTOT * DI) / 256, 256>>>(conv_w + i * DI * DCONV,
                                                     conv_b + i * DI);

        // 4) x_proj: (B*L,512) x (48,512)^T -> (B*L,48)
        {
            dim3 g(1, MTOT / 64);
            gemm_nt<<<g, 256>>>(xc, xp_w + (size_t)i * 48 * DI, xdbl,
                                MTOT, 48, DI, 0);
        }

        // 5) dt projection + softplus
        dtproj_kernel<<<2 * MTOT, 256>>>(dtp_w + i * DI * DTR, dtp_b + i * DI);

        // 6) selective scan + D skip + z gate -> y
        {
            dim3 g(B_SZ, DI / 128);
            scan_kernel<<<g, 256>>>(A_log + i * DI * DS, Dp + i * DI);
        }

        // 7) out_proj: (B*L,512) x (256,512)^T -> transposed to (B,256,L)
        {
            dim3 g(CH / 64, MTOT / 64);
            gemm_nt<<<g, 256>>>(yy, out_w + (size_t)i * CH * DI, xout,
                                MTOT, CH, DI, 1);
        }
    }
}

// round 2
// speedup vs baseline: 1.0764x; 1.0764x over previous
#include <cuda_runtime.h>
#include <math.h>
#include <stdint.h>

#define B_SZ   32
#define CH     256
#define L_SEQ  784
#define DI     512
#define DS     16
#define DCONV  4
#define DTR    16
#define MTOT   (B_SZ * L_SEQ)   // 25088

// ---------------- scratch (static __device__, no allocation) ----------------
__device__ float g_xn  [(size_t)MTOT * CH];        // layernormed, (B*L, C)
__device__ float g_xz  [(size_t)MTOT * 2 * DI];    // in_proj out, (B*L, 1024)
__device__ float g_xc  [(size_t)MTOT * DI];        // conv+silu out
__device__ float g_xdbl[(size_t)MTOT * 48];        // x_proj out (dt_r | B | C)
__device__ float g_dt  [(size_t)MTOT * DI];        // softplus(dt)
__device__ float g_y   [(size_t)MTOT * DI];        // scan output (gated)
__device__ float g_xbuf[(size_t)B_SZ * CH * L_SEQ];// inter-depth activations (B,C,L)

// ============================================================================
// tf32 helpers
// ============================================================================
__device__ __forceinline__ uint32_t f2tf32(float x) {
    uint32_t r;
    asm("cvt.rna.tf32.f32 %0, %1;" : "=r"(r) : "f"(x));
    return r;
}
// split x into hi (tf32) and lo (tf32 of residual)
__device__ __forceinline__ void tf32_split(float x, float& hi, float& lo) {
    uint32_t h = f2tf32(x);
    float hf = __uint_as_float(h);
    hi = hf;
    lo = __uint_as_float(f2tf32(x - hf));
}
__device__ __forceinline__ void mma_tf32(float* c,
                                         uint32_t a0, uint32_t a1, uint32_t a2, uint32_t a3,
                                         uint32_t b0, uint32_t b1) {
    asm volatile("mma.sync.aligned.m16n8k8.row.col.f32.tf32.tf32.f32 "
                 "{%0,%1,%2,%3}, {%4,%5,%6,%7}, {%8,%9}, {%0,%1,%2,%3};\n"
                 : "+f"(c[0]), "+f"(c[1]), "+f"(c[2]), "+f"(c[3])
                 : "r"(a0), "r"(a1), "r"(a2), "r"(a3), "r"(b0), "r"(b1));
}

// ============================================================================
// Tensor-core GEMM: C[M,N] = A[M,K] * B[N,K]^T   (fp32 in/out, 3x tf32 split)
// BM=128 BN=64 BK=16, 256 threads, warps 2(m) x 4(n), warp tile 64x16.
// transOut=1 writes C in (B, N, L) layout via smem transpose (coalesced).
// M must be a multiple of 128; K a multiple of 16. N guarded.
// ============================================================================
#define BKP 20   // padded BK stride (conflict-free fragment loads)

struct GSm {
    float Ah[128][BKP];
    float Al[128][BKP];
    float Bh[64][BKP];
    float Bl[64][BKP];
};
union USm {
    GSm   g;
    float ct[64][132];   // epilogue transpose buffer (33792 B)
};

__global__ void __launch_bounds__(256)
gemm_tc(const float* __restrict__ A, const float* __restrict__ Bw,
        float* __restrict__ C, int M, int N, int K, int transOut) {
    __shared__ USm sm;

    const int tid = threadIdx.x;
    const int bm  = blockIdx.y * 128;
    const int bn  = blockIdx.x * 64;

    const int warp = tid >> 5, lane = tid & 31;
    const int wm = warp & 1, wn = warp >> 1;       // 2 x 4 warp grid
    const int r  = lane >> 2, cc = lane & 3;       // fragment lane coords

    // loader coords: row = tid/4 (0..63), q = tid%4 (float4 column)
    const int lrow = tid >> 2, lq = tid & 3;
    const int rb   = min(bn + lrow, N - 1);        // clamp (x_proj N=48)

    float acc[4][2][4];
    #pragma unroll
    for (int i = 0; i < 4; i++)
        #pragma unroll
        for (int j = 0; j < 2; j++)
            #pragma unroll
            for (int v = 0; v < 4; v++) acc[i][j][v] = 0.0f;

    const int KT = K >> 4;
    float4 ra0, ra1, rbv;

    // prologue global load (stage 0)
    {
        const float* pa = A + (size_t)(bm + lrow) * K + lq * 4;
        ra0 = *reinterpret_cast<const float4*>(pa);
        ra1 = *reinterpret_cast<const float4*>(pa + (size_t)64 * K);
        rbv = *reinterpret_cast<const float4*>(Bw + (size_t)rb * K + lq * 4);
    }

    for (int kt = 0; kt < KT; kt++) {
        __syncthreads();   // consumers done with smem
        // ---- producer: cvt hi/lo, store to smem ----
        {
            float h, l;
            float* ah0 = &sm.g.Ah[lrow][lq * 4];
            float* al0 = &sm.g.Al[lrow][lq * 4];
            tf32_split(ra0.x, h, l); ah0[0] = h; al0[0] = l;
            tf32_split(ra0.y, h, l); ah0[1] = h; al0[1] = l;
            tf32_split(ra0.z, h, l); ah0[2] = h; al0[2] = l;
            tf32_split(ra0.w, h, l); ah0[3] = h; al0[3] = l;
            float* ah1 = &sm.g.Ah[lrow + 64][lq * 4];
            float* al1 = &sm.g.Al[lrow + 64][lq * 4];
            tf32_split(ra1.x, h, l); ah1[0] = h; al1[0] = l;
            tf32_split(ra1.y, h, l); ah1[1] = h; al1[1] = l;
            tf32_split(ra1.z, h, l); ah1[2] = h; al1[2] = l;
            tf32_split(ra1.w, h, l); ah1[3] = h; al1[3] = l;
            float* bh = &sm.g.Bh[lrow][lq * 4];
            float* bl = &sm.g.Bl[lrow][lq * 4];
            tf32_split(rbv.x, h, l); bh[0] = h; bl[0] = l;
            tf32_split(rbv.y, h, l); bh[1] = h; bl[1] = l;
            tf32_split(rbv.z, h, l); bh[2] = h; bl[2] = l;
            tf32_split(rbv.w, h, l); bh[3] = h; bl[3] = l;
        }
        __syncthreads();

        // ---- prefetch next stage ----
        if (kt + 1 < KT) {
            int k0 = (kt + 1) << 4;
            const float* pa = A + (size_t)(bm + lrow) * K + k0 + lq * 4;
            ra0 = *reinterpret_cast<const float4*>(pa);
            ra1 = *reinterpret_cast<const float4*>(pa + (size_t)64 * K);
            rbv = *reinterpret_cast<const float4*>(Bw + (size_t)rb * K + k0 + lq * 4);
        }

        // ---- consumer: pure LDS + HMMA ----
        #pragma unroll
        for (int kk = 0; kk < 16; kk += 8) {
            uint32_t bh[2][2], bl[2][2];
            #pragma unroll
            for (int ni = 0; ni < 2; ni++) {
                int n0 = wn * 16 + ni * 8;
                bh[ni][0] = __float_as_uint(sm.g.Bh[n0 + r][kk + cc]);
                bh[ni][1] = __float_as_uint(sm.g.Bh[n0 + r][kk + 4 + cc]);
                bl[ni][0] = __float_as_uint(sm.g.Bl[n0 + r][kk + cc]);
                bl[ni][1] = __float_as_uint(sm.g.Bl[n0 + r][kk + 4 + cc]);
            }
            #pragma unroll
            for (int mi = 0; mi < 4; mi++) {
                int m0 = wm * 64 + mi * 16;
                uint32_t ah0 = __float_as_uint(sm.g.Ah[m0 + r][kk + cc]);
                uint32_t ah1 = __float_as_uint(sm.g.Ah[m0 + r + 8][kk + cc]);
                uint32_t ah2 = __float_as_uint(sm.g.Ah[m0 + r][kk + 4 + cc]);
                uint32_t ah3 = __float_as_uint(sm.g.Ah[m0 + r + 8][kk + 4 + cc]);
                uint32_t al0 = __float_as_uint(sm.g.Al[m0 + r][kk + cc]);
                uint32_t al1 = __float_as_uint(sm.g.Al[m0 + r + 8][kk + cc]);
                uint32_t al2 = __float_as_uint(sm.g.Al[m0 + r][kk + 4 + cc]);
                uint32_t al3 = __float_as_uint(sm.g.Al[m0 + r + 8][kk + 4 + cc]);
                #pragma unroll
                for (int ni = 0; ni < 2; ni++) {
                    mma_tf32(acc[mi][ni], ah0, ah1, ah2, ah3, bh[ni][0], bh[ni][1]);
                    mma_tf32(acc[mi][ni], al0, al1, al2, al3, bh[ni][0], bh[ni][1]);
                    mma_tf32(acc[mi][ni], ah0, ah1, ah2, ah3, bl[ni][0], bl[ni][1]);
                }
            }
        }
    }

    if (!transOut) {
        // direct store: float2 pairs, guard col < N
        #pragma unroll
        for (int mi = 0; mi < 4; mi++) {
            int row0 = bm + wm * 64 + mi * 16 + r;
            #pragma unroll
            for (int ni = 0; ni < 2; ni++) {
                int col = bn + wn * 16 + ni * 8 + 2 * cc;
                if (col < N) {
                    float2 v0 = make_float2(acc[mi][ni][0], acc[mi][ni][1]);
                    float2 v1 = make_float2(acc[mi][ni][2], acc[mi][ni][3]);
                    *reinterpret_cast<float2*>(C + (size_t)row0 * N + col) = v0;
                    *reinterpret_cast<float2*>(C + (size_t)(row0 + 8) * N + col) = v1;
                }
            }
        }
    } else {
        // transpose through smem, then coalesced (B,N,L) stores
        __syncthreads();
        #pragma unroll
        for (int mi = 0; mi < 4; mi++) {
            int m0 = wm * 64 + mi * 16 + r;
            #pragma unroll
            for (int ni = 0; ni < 2; ni++) {
                int n0 = wn * 16 + ni * 8 + 2 * cc;
                sm.ct[n0][m0]         = acc[mi][ni][0];
                sm.ct[n0 + 1][m0]     = acc[mi][ni][1];
                sm.ct[n0][m0 + 8]     = acc[mi][ni][2];
                sm.ct[n0 + 1][m0 + 8] = acc[mi][ni][3];
            }
        }
        __syncthreads();
        for (int i = tid; i < 64 * 128; i += 256) {
            int n = i >> 7, m = i & 127;
            int row = bm + m;
            int b = row / L_SEQ;
            int l = row - b * L_SEQ;
            C[((size_t)b * N + bn + n) * L_SEQ + l] = sm.ct[n][m];
        }
    }
}

// ---------------- LayerNorm, coalesced, (B,C,L) -> (B*L, C) ------------------
// grid (49, 32): 16 l's per block, 256 threads.
__global__ void ln_kernel(const float* __restrict__ x,
                          const float* __restrict__ w,
                          const float* __restrict__ bb,
                          float* __restrict__ out) {
    __shared__ float s[256][17];
    int l0 = blockIdx.x * 16;
    int b  = blockIdx.y;
    int tid = threadIdx.x;

    for (int i = tid; i < 256 * 16; i += 256) {
        int c = i >> 4, l = i & 15;
        s[c][l] = x[((size_t)b * CH + c) * L_SEQ + l0 + l];
    }
    __syncthreads();

    int l = tid >> 4, part = tid & 15;
    float a = 0.f, q = 0.f;
    #pragma unroll
    for (int j = 0; j < 16; j++) {
        float v = s[part + 16 * j][l];
        a += v;
        q = fmaf(v, v, q);
    }
    #pragma unroll
    for (int o = 1; o < 16; o <<= 1) {
        a += __shfl_xor_sync(0xffffffffu, a, o);
        q += __shfl_xor_sync(0xffffffffu, q, o);
    }
    float mu  = a * (1.0f / CH);
    float var = q * (1.0f / CH) - mu * mu;
    float inv = rsqrtf(var + 1e-5f);

    size_t base = (size_t)(b * L_SEQ + l0 + l) * CH;
    #pragma unroll
    for (int j = 0; j < 16; j++) {
        int c = part + 16 * j;
        out[base + c] = (s[c][l] - mu) * inv * w[c] + bb[c];
    }
}

// ---------------- causal depthwise conv (k=4) + SiLU --------------------------
__global__ void conv_silu_kernel(const float* __restrict__ cw,
                                 const float* __restrict__ cb) {
    int idx = blockIdx.x * 256 + threadIdx.x;
    int d  = idx & (DI - 1);
    int bl = idx >> 9;
    int l  = bl % L_SEQ;
    float acc = cb[d];
    #pragma unroll
    for (int k = 0; k < DCONV; k++) {
        int ll = l - 3 + k;
        if (ll >= 0)
            acc = fmaf(g_xz[(size_t)(bl - 3 + k) * (2 * DI) + d], cw[d * DCONV + k], acc);
    }
    acc = acc / (1.0f + __expf(-acc));
    g_xc[(size_t)idx] = acc;
}

// ---------------- dt = softplus(dt_r @ W^T + b) --------------------------------
__global__ void dtproj_kernel(const float* __restrict__ dtw,
                              const float* __restrict__ dtb) {
    int blk = blockIdx.x;
    int bl  = blk >> 1;
    int d   = ((blk & 1) << 8) + threadIdx.x;
    __shared__ float rr[DTR];
    if (threadIdx.x < DTR) rr[threadIdx.x] = g_xdbl[(size_t)bl * 48 + threadIdx.x];
    __syncthreads();
    float acc = dtb[d];
    #pragma unroll
    for (int i = 0; i < DTR; i++) acc = fmaf(rr[i], dtw[d * DTR + i], acc);
    acc = (acc > 20.0f) ? acc : log1pf(__expf(acc));
    g_dt[(size_t)bl * DI + d] = acc;
}

// ---------------- selective scan, 2 threads per (b,d), 8 states each ----------
__global__ void scan_kernel(const float* __restrict__ A_log,
                            const float* __restrict__ Dp) {
    int b    = blockIdx.x;
    int tid  = threadIdx.x;
    int dl   = tid >> 1, half = tid & 1;
    int d    = blockIdx.y * 128 + dl;

    float a[8];
    #pragma unroll
    for (int s = 0; s < 8; s++) a[s] = -__expf(A_log[d * DS + half * 8 + s]);
    float Dd = Dp[d];

    float h[8];
    #pragma unroll
    for (int s = 0; s < 8; s++) h[s] = 0.0f;

    __shared__ float sBC[16][32];

    for (int c0 = 0; c0 < L_SEQ; c0 += 16) {
        __syncthreads();
        for (int i = tid; i < 16 * 32; i += 256) {
            int st = i >> 5, j = i & 31;
            sBC[st][j] = g_xdbl[((size_t)b * L_SEQ + c0 + st) * 48 + 16 + j];
        }
        __syncthreads();
        #pragma unroll 4
        for (int st = 0; st < 16; st++) {
            size_t row = (size_t)b * L_SEQ + c0 + st;
            float dtv = g_dt[row * DI + d];
            float xv  = g_xc[row * DI + d];
            float dtx = dtv * xv;
            float yacc = 0.0f;
            #pragma unroll
            for (int s = 0; s < 8; s++) {
                float dA = __expf(dtv * a[s]);
                h[s] = fmaf(h[s], dA, dtx * sBC[st][half * 8 + s]);
                yacc = fmaf(h[s], sBC[st][16 + half * 8 + s], yacc);
            }
            yacc += __shfl_xor_sync(0xffffffffu, yacc, 1);
            if (half == 0) {
                float zv = g_xz[row * 2 * DI + DI + d];
                float yf = fmaf(xv, Dd, yacc) * (zv / (1.0f + __expf(-zv)));
                g_y[row * DI + d] = yf;
            }
        }
    }
}

// ------------------------------- launcher -------------------------------------
extern "C" void kernel_launch(void* const* d_in, const int* in_sizes, int n_in,
                              void* d_out, int out_size) {
    const float* bbox   = (const float*)d_in[0];
    const float* norm_w = (const float*)d_in[1];
    const float* norm_b = (const float*)d_in[2];
    const float* in_w   = (const float*)d_in[3];
    const float* conv_w = (const float*)d_in[4];
    const float* conv_b = (const float*)d_in[5];
    const float* xp_w   = (const float*)d_in[6];
    const float* dtp_w  = (const float*)d_in[7];
    const float* dtp_b  = (const float*)d_in[8];
    const float* A_log  = (const float*)d_in[9];
    const float* Dp     = (const float*)d_in[10];
    const float* out_w  = (const float*)d_in[11];
    float* out = (float*)d_out;

    float *xn, *xz, *xc, *xdbl, *yy, *xbuf;
    cudaGetSymbolAddress((void**)&xn,   g_xn);
    cudaGetSymbolAddress((void**)&xz,   g_xz);
    cudaGetSymbolAddress((void**)&xc,   g_xc);
    cudaGetSymbolAddress((void**)&xdbl, g_xdbl);
    cudaGetSymbolAddress((void**)&yy,   g_y);
    cudaGetSymbolAddress((void**)&xbuf, g_xbuf);

    for (int i = 0; i < 2; i++) {
        const float* xin = (i == 0) ? bbox : xbuf;
        float* xout      = (i == 0) ? xbuf : out;

        // 1) layernorm + layout change (B,C,L) -> (B*L,C)
        {
            dim3 g(49, 32);
            ln_kernel<<<g, 256>>>(xin, norm_w + i * CH, norm_b + i * CH, xn);
        }

        // 2) in_proj: (25088,256) x (1024,256)^T -> (25088,1024)
        {
            dim3 g(2 * DI / 64, MTOT / 128);
            gemm_tc<<<g, 256>>>(xn, in_w + (size_t)i * 2 * DI * CH, xz,
                                MTOT, 2 * DI, CH, 0);
        }

        // 3) causal conv + silu -> xc
        conv_silu_kernel<<<(MTOT * DI) / 256, 256>>>(conv_w + i * DI * DCONV,
                                                     conv_b + i * DI);

        // 4) x_proj: (25088,512) x (48,512)^T -> (25088,48)
        {
            dim3 g(1, MTOT / 128);
            gemm_tc<<<g, 256>>>(xc, xp_w + (size_t)i * 48 * DI, xdbl,
                                MTOT, 48, DI, 0);
        }

        // 5) dt projection + softplus
        dtproj_kernel<<<2 * MTOT, 256>>>(dtp_w + i * DI * DTR, dtp_b + i * DI);

        // 6) selective scan + D skip + z gate -> y
        {
            dim3 g(B_SZ, DI / 128);
            scan_kernel<<<g, 256>>>(A_log + i * DI * DS, Dp + i * DI);
        }

        // 7) out_proj: (25088,512) x (256,512)^T -> (B,256,L) transposed
        {
            dim3 g(CH / 64, MTOT / 128);
            gemm_tc<<<g, 256>>>(yy, out_w + (size_t)i * CH * DI, xout,
                                MTOT, CH, DI, 1);
        }
    }
}

// round 3
// speedup vs baseline: 1.1133x; 1.0343x over previous
#include <cuda_runtime.h>
#include <math.h>
#include <stdint.h>

#define B_SZ   32
#define CH     256
#define L_SEQ  784
#define DI     512
#define DS     16
#define DCONV  4
#define DTR    16
#define MTOT   (B_SZ * L_SEQ)   // 25088

// ---------------- scratch (static __device__, no allocation) ----------------
__device__ float g_xn  [(size_t)MTOT * CH];
__device__ float g_xz  [(size_t)MTOT * 2 * DI];
__device__ float g_xc  [(size_t)MTOT * DI];
__device__ float g_xdbl[(size_t)MTOT * 48];
__device__ float g_dt  [(size_t)MTOT * DI];
__device__ float g_y   [(size_t)MTOT * DI];
__device__ float g_xbuf[(size_t)B_SZ * CH * L_SEQ];

// ============================================================================
// tf32 helpers
// ============================================================================
__device__ __forceinline__ float f2tf32f(float x) {
    uint32_t r;
    asm("cvt.rna.tf32.f32 %0, %1;" : "=r"(r) : "f"(x));
    return __uint_as_float(r);
}
__device__ __forceinline__ void tf32_split(float x, float& hi, float& lo) {
    hi = f2tf32f(x);
    lo = f2tf32f(x - hi);
}
__device__ __forceinline__ void mma_tf32(float* c,
                                         float a0, float a1, float a2, float a3,
                                         float b0, float b1) {
    asm volatile("mma.sync.aligned.m16n8k8.row.col.f32.tf32.tf32.f32 "
                 "{%0,%1,%2,%3}, {%4,%5,%6,%7}, {%8,%9}, {%0,%1,%2,%3};\n"
                 : "+f"(c[0]), "+f"(c[1]), "+f"(c[2]), "+f"(c[3])
                 : "r"(__float_as_uint(a0)), "r"(__float_as_uint(a1)),
                   "r"(__float_as_uint(a2)), "r"(__float_as_uint(a3)),
                   "r"(__float_as_uint(b0)), "r"(__float_as_uint(b1)));
}

// ============================================================================
// GEMM C[M,N] = A[M,K]*B[N,K]^T, fp32 via 3-term tf32 split.
// BM=128, BN=NI*32, BK=16, 256 threads, warps 2(m) x 4(n).
// Fragment-major smem: float4 = (hi_c4=0, hi_c4=1, lo_c4=0, lo_c4=1),
// lane-linear -> conflict-free LDS.128/STS.128. Double-buffered, 1 sync/tile.
// ============================================================================
template<int NI, int TRANS>
__global__ void __launch_bounds__(256)
gemm_tc(const float* __restrict__ A, const float* __restrict__ Bw,
        float* __restrict__ C, int M, int N, int K) {
    constexpr int BN    = NI * 32;
    constexpr int AF4   = 8 * 2 * 2 * 32;        // A float4s per stage (1024)
    constexpr int BF4   = (BN / 8) * 2 * 32;     // B float4s per stage
    constexpr int STAGE = AF4 + BF4;
    constexpr int NB    = (NI == 4) ? 2 : 1;     // B rows per producer thread

    extern __shared__ float4 sm4[];

    const int tid  = threadIdx.x;
    const int bm   = blockIdx.y * 128;
    const int bn   = blockIdx.x * BN;
    const int warp = tid >> 5, lane = tid & 31;
    const int wm   = warp & 1, wn = warp >> 1;
    const int r    = lane >> 2, cc = lane & 3;

    const int prow = tid >> 2, pcc = tid & 3;    // producer coords

    float acc[4][NI][4];
    #pragma unroll
    for (int i = 0; i < 4; i++)
        #pragma unroll
        for (int j = 0; j < NI; j++)
            #pragma unroll
            for (int v = 0; v < 4; v++) acc[i][j][v] = 0.0f;

    const int KT = K >> 4;
    float va[2][2][2];       // [rowhalf][ks][c4]
    float vb[NB][2][2];

    // ---- prologue global load (tile 0) ----
    {
        #pragma unroll
        for (int rr = 0; rr < 2; rr++) {
            const float* p = A + (size_t)(bm + prow + rr * 64) * K + pcc;
            #pragma unroll
            for (int ks = 0; ks < 2; ks++)
                #pragma unroll
                for (int c4 = 0; c4 < 2; c4++)
                    va[rr][ks][c4] = p[ks * 8 + c4 * 4];
        }
        #pragma unroll
        for (int rr = 0; rr < NB; rr++) {
            int nb = min(bn + prow + rr * 64, N - 1);
            const float* p = Bw + (size_t)nb * K + pcc;
            #pragma unroll
            for (int ks = 0; ks < 2; ks++)
                #pragma unroll
                for (int c4 = 0; c4 < 2; c4++)
                    vb[rr][ks][c4] = p[ks * 8 + c4 * 4];
        }
    }

    for (int kt = 0; kt < KT; kt++) {
        const int s = kt & 1;
        float4* sa = sm4 + s * STAGE;
        float4* sb = sa + AF4;

        // ---- producer: split + STS.128 (lane-linear, conflict-free) ----
        #pragma unroll
        for (int rr = 0; rr < 2; rr++) {
            int row = prow + rr * 64;
            int mc = row >> 4, r8 = (row >> 3) & 1, ln = (row & 7) * 4 + pcc;
            #pragma unroll
            for (int ks = 0; ks < 2; ks++) {
                float h0, l0, h1, l1;
                tf32_split(va[rr][ks][0], h0, l0);
                tf32_split(va[rr][ks][1], h1, l1);
                sa[((mc * 2 + ks) * 2 + r8) * 32 + ln] = make_float4(h0, h1, l0, l1);
            }
        }
        #pragma unroll
        for (int rr = 0; rr < NB; rr++) {
            int n = prow + rr * 64;
            int nc = n >> 3, ln = (n & 7) * 4 + pcc;
            #pragma unroll
            for (int ks = 0; ks < 2; ks++) {
                float h0, l0, h1, l1;
                tf32_split(vb[rr][ks][0], h0, l0);
                tf32_split(vb[rr][ks][1], h1, l1);
                sb[(nc * 2 + ks) * 32 + ln] = make_float4(h0, h1, l0, l1);
            }
        }

        // ---- prefetch next tile into regs ----
        if (kt + 1 < KT) {
            int k0 = (kt + 1) << 4;
            #pragma unroll
            for (int rr = 0; rr < 2; rr++) {
                const float* p = A + (size_t)(bm + prow + rr * 64) * K + k0 + pcc;
                #pragma unroll
                for (int ks = 0; ks < 2; ks++)
                    #pragma unroll
                    for (int c4 = 0; c4 < 2; c4++)
                        va[rr][ks][c4] = p[ks * 8 + c4 * 4];
            }
            #pragma unroll
            for (int rr = 0; rr < NB; rr++) {
                int nb = min(bn + prow + rr * 64, N - 1);
                const float* p = Bw + (size_t)nb * K + k0 + pcc;
                #pragma unroll
                for (int ks = 0; ks < 2; ks++)
                    #pragma unroll
                    for (int c4 = 0; c4 < 2; c4++)
                        vb[rr][ks][c4] = p[ks * 8 + c4 * 4];
            }
        }

        __syncthreads();

        // ---- consumer: LDS.128 frags + 3-term mma ----
        #pragma unroll
        for (int ks = 0; ks < 2; ks++) {
            float4 bf[NI];
            #pragma unroll
            for (int ni = 0; ni < NI; ni++)
                bf[ni] = sb[((wn * NI + ni) * 2 + ks) * 32 + lane];
            #pragma unroll
            for (int mi = 0; mi < 4; mi++) {
                float4 f0 = sa[(((wm * 4 + mi) * 2 + ks) * 2 + 0) * 32 + lane];
                float4 f1 = sa[(((wm * 4 + mi) * 2 + ks) * 2 + 1) * 32 + lane];
                #pragma unroll
                for (int ni = 0; ni < NI; ni++) {
                    mma_tf32(acc[mi][ni], f0.x, f1.x, f0.y, f1.y, bf[ni].x, bf[ni].y);
                    mma_tf32(acc[mi][ni], f0.z, f1.z, f0.w, f1.w, bf[ni].x, bf[ni].y);
                    mma_tf32(acc[mi][ni], f0.x, f1.x, f0.y, f1.y, bf[ni].z, bf[ni].w);
                }
            }
        }
    }

    if (!TRANS) {
        #pragma unroll
        for (int mi = 0; mi < 4; mi++) {
            int row0 = bm + wm * 64 + mi * 16 + r;
            #pragma unroll
            for (int ni = 0; ni < NI; ni++) {
                int col = bn + wn * (NI * 8) + ni * 8 + 2 * cc;
                if (col < N) {
                    *reinterpret_cast<float2*>(C + (size_t)row0 * N + col) =
                        make_float2(acc[mi][ni][0], acc[mi][ni][1]);
                    *reinterpret_cast<float2*>(C + (size_t)(row0 + 8) * N + col) =
                        make_float2(acc[mi][ni][2], acc[mi][ni][3]);
                }
            }
        }
    } else {
        // transpose 64 n-columns at a time through smem -> coalesced (B,N,L)
        float* ct = reinterpret_cast<float*>(sm4);
        __syncthreads();
        #pragma unroll
        for (int half = 0; half < 2; half++) {
            if ((wn >> 1) == half) {
                #pragma unroll
                for (int mi = 0; mi < 4; mi++) {
                    int m0 = wm * 64 + mi * 16 + r;
                    #pragma unroll
                    for (int ni = 0; ni < NI; ni++) {
                        int n0 = (wn - half * 2) * 32 + ni * 8 + 2 * cc;
                        ct[(n0    ) * 132 + m0    ] = acc[mi][ni][0];
                        ct[(n0 + 1) * 132 + m0    ] = acc[mi][ni][1];
                        ct[(n0    ) * 132 + m0 + 8] = acc[mi][ni][2];
                        ct[(n0 + 1) * 132 + m0 + 8] = acc[mi][ni][3];
                    }
                }
            }
            __syncthreads();
            for (int i = tid; i < 64 * 128; i += 256) {
                int n = i >> 7, m = i & 127;
                int row = bm + m;
                int b = row / L_SEQ;
                int l = row - b * L_SEQ;
                C[((size_t)b * N + bn + half * 64 + n) * L_SEQ + l] = ct[n * 132 + m];
            }
            __syncthreads();
        }
    }
}

// ---------------- LayerNorm, coalesced, (B,C,L) -> (B*L, C) ------------------
__global__ void ln_kernel(const float* __restrict__ x,
                          const float* __restrict__ w,
                          const float* __restrict__ bb,
                          float* __restrict__ out) {
    __shared__ float s[256][17];
    int l0 = blockIdx.x * 16;
    int b  = blockIdx.y;
    int tid = threadIdx.x;

    for (int i = tid; i < 256 * 16; i += 256) {
        int c = i >> 4, l = i & 15;
        s[c][l] = x[((size_t)b * CH + c) * L_SEQ + l0 + l];
    }
    __syncthreads();

    int l = tid >> 4, part = tid & 15;
    float a = 0.f, q = 0.f;
    #pragma unroll
    for (int j = 0; j < 16; j++) {
        float v = s[part + 16 * j][l];
        a += v;
        q = fmaf(v, v, q);
    }
    #pragma unroll
    for (int o = 1; o < 16; o <<= 1) {
        a += __shfl_xor_sync(0xffffffffu, a, o);
        q += __shfl_xor_sync(0xffffffffu, q, o);
    }
    float mu  = a * (1.0f / CH);
    float var = q * (1.0f / CH) - mu * mu;
    float inv = rsqrtf(var + 1e-5f);

    size_t base = (size_t)(b * L_SEQ + l0 + l) * CH;
    #pragma unroll
    for (int j = 0; j < 16; j++) {
        int c = part + 16 * j;
        out[base + c] = (s[c][l] - mu) * inv * w[c] + bb[c];
    }
}

// ---------------- causal depthwise conv (k=4) + SiLU --------------------------
__global__ void conv_silu_kernel(const float* __restrict__ cw,
                                 const float* __restrict__ cb) {
    int idx = blockIdx.x * 256 + threadIdx.x;
    int d  = idx & (DI - 1);
    int bl = idx >> 9;
    int l  = bl % L_SEQ;
    float acc = cb[d];
    #pragma unroll
    for (int k = 0; k < DCONV; k++) {
        int ll = l - 3 + k;
        if (ll >= 0)
            acc = fmaf(g_xz[(size_t)(bl - 3 + k) * (2 * DI) + d], cw[d * DCONV + k], acc);
    }
    acc = acc / (1.0f + __expf(-acc));
    g_xc[(size_t)idx] = acc;
}

// ---------------- dt = softplus(dt_r @ W^T + b) --------------------------------
__global__ void dtproj_kernel(const float* __restrict__ dtw,
                              const float* __restrict__ dtb) {
    int blk = blockIdx.x;
    int bl  = blk >> 1;
    int d   = ((blk & 1) << 8) + threadIdx.x;
    __shared__ float rr[DTR];
    if (threadIdx.x < DTR) rr[threadIdx.x] = g_xdbl[(size_t)bl * 48 + threadIdx.x];
    __syncthreads();
    float acc = dtb[d];
    #pragma unroll
    for (int i = 0; i < DTR; i++) acc = fmaf(rr[i], dtw[d * DTR + i], acc);
    acc = (acc > 20.0f) ? acc : log1pf(__expf(acc));
    g_dt[(size_t)bl * DI + d] = acc;
}

// ---------------- selective scan: 2 thr/(b,d), pow-chain exp -------------------
__global__ void scan_kernel(const float* __restrict__ A_log,
                            const float* __restrict__ Dp) {
    int b    = blockIdx.x;
    int tid  = threadIdx.x;                 // 128
    int dl   = tid >> 1, half = tid & 1;
    int d    = blockIdx.y * 64 + dl;

    float a[8];
    bool powok = true;
    #pragma unroll
    for (int s = 0; s < 8; s++) {
        a[s] = -__expf(A_log[d * DS + half * 8 + s]);
        float kf = (float)(half * 8 + s + 1);
        powok = powok && (fabsf(-a[s] - kf) < 1e-3f * kf);
    }
    float Dd = Dp[d];

    float h[8];
    #pragma unroll
    for (int s = 0; s < 8; s++) h[s] = 0.0f;

    __shared__ float sBC[16][32];

    for (int c0 = 0; c0 < L_SEQ; c0 += 16) {
        __syncthreads();
        for (int i = tid; i < 16 * 32; i += 128) {
            int st = i >> 5, j = i & 31;
            sBC[st][j] = g_xdbl[((size_t)b * L_SEQ + c0 + st) * 48 + 16 + j];
        }
        __syncthreads();
        #pragma unroll 4
        for (int st = 0; st < 16; st++) {
            size_t row = (size_t)b * L_SEQ + c0 + st;
            float dtv = g_dt[row * DI + d];
            float xv  = g_xc[row * DI + d];
            float dtx = dtv * xv;
            float dA[8];
            if (powok) {
                float rr = __expf(-dtv);
                float r2 = rr * rr, r4 = r2 * r2, r8v = r4 * r4;
                float p = half ? r8v : 1.0f;
                #pragma unroll
                for (int s = 0; s < 8; s++) { p *= rr; dA[s] = p; }
            } else {
                #pragma unroll
                for (int s = 0; s < 8; s++) dA[s] = __expf(dtv * a[s]);
            }
            float yacc = 0.0f;
            #pragma unroll
            for (int s = 0; s < 8; s++) {
                h[s] = fmaf(h[s], dA[s], dtx * sBC[st][half * 8 + s]);
                yacc = fmaf(h[s], sBC[st][16 + half * 8 + s], yacc);
            }
            yacc += __shfl_xor_sync(0xffffffffu, yacc, 1);
            if (half == 0) {
                float zv = g_xz[row * 2 * DI + DI + d];
                float yf = fmaf(xv, Dd, yacc) * (zv / (1.0f + __expf(-zv)));
                g_y[row * DI + d] = yf;
            }
        }
    }
}

// ------------------------------- launcher -------------------------------------
extern "C" void kernel_launch(void* const* d_in, const int* in_sizes, int n_in,
                              void* d_out, int out_size) {
    const float* bbox   = (const float*)d_in[0];
    const float* norm_w = (const float*)d_in[1];
    const float* norm_b = (const float*)d_in[2];
    const float* in_w   = (const float*)d_in[3];
    const float* conv_w = (const float*)d_in[4];
    const float* conv_b = (const float*)d_in[5];
    const float* xp_w   = (const float*)d_in[6];
    const float* dtp_w  = (const float*)d_in[7];
    const float* dtp_b  = (const float*)d_in[8];
    const float* A_log  = (const float*)d_in[9];
    const float* Dp     = (const float*)d_in[10];
    const float* out_w  = (const float*)d_in[11];
    float* out = (float*)d_out;

    cudaFuncSetAttribute(gemm_tc<4,0>, cudaFuncAttributeMaxDynamicSharedMemorySize, 65536);
    cudaFuncSetAttribute(gemm_tc<4,1>, cudaFuncAttributeMaxDynamicSharedMemorySize, 65536);
    cudaFuncSetAttribute(gemm_tc<2,0>, cudaFuncAttributeMaxDynamicSharedMemorySize, 49152);

    float *xn, *xz, *xc, *xdbl, *yy, *xbuf;
    cudaGetSymbolAddress((void**)&xn,   g_xn);
    cudaGetSymbolAddress((void**)&xz,   g_xz);
    cudaGetSymbolAddress((void**)&xc,   g_xc);
    cudaGetSymbolAddress((void**)&xdbl, g_xdbl);
    cudaGetSymbolAddress((void**)&yy,   g_y);
    cudaGetSymbolAddress((void**)&xbuf, g_xbuf);

    for (int i = 0; i < 2; i++) {
        const float* xin = (i == 0) ? bbox : xbuf;
        float* xout      = (i == 0) ? xbuf : out;

        {   // layernorm
            dim3 g(49, 32);
            ln_kernel<<<g, 256>>>(xin, norm_w + i * CH, norm_b + i * CH, xn);
        }
        {   // in_proj: (25088,256)x(1024,256)^T
            dim3 g(1024 / 128, MTOT / 128);
            gemm_tc<4,0><<<g, 256, 65536>>>(xn, in_w + (size_t)i * 2 * DI * CH, xz,
                                            MTOT, 2 * DI, CH);
        }
        // conv + silu
        conv_silu_kernel<<<(MTOT * DI) / 256, 256>>>(conv_w + i * DI * DCONV,
                                                     conv_b + i * DI);
        {   // x_proj: (25088,512)x(48,512)^T
            dim3 g(1, MTOT / 128);
            gemm_tc<2,0><<<g, 256, 49152>>>(xc, xp_w + (size_t)i * 48 * DI, xdbl,
                                            MTOT, 48, DI);
        }
        // dt projection
        dtproj_kernel<<<2 * MTOT, 256>>>(dtp_w + i * DI * DTR, dtp_b + i * DI);
        {   // selective scan
            dim3 g(B_SZ, DI / 64);
            scan_kernel<<<g, 128>>>(A_log + i * DI * DS, Dp + i * DI);
        }
        {   // out_proj: (25088,512)x(256,512)^T -> (B,256,L)
            dim3 g(256 / 128, MTOT / 128);
            gemm_tc<4,1><<<g, 256, 65536>>>(yy, out_w + (size_t)i * CH * DI, xout,
                                            MTOT, CH, DI);
        }
    }
}

// round 4
// speedup vs baseline: 1.7539x; 1.5753x over previous
#include <cuda_runtime.h>
#include <cuda_bf16.h>
#include <math.h>
#include <stdint.h>

#define B_SZ   32
#define CH     256
#define L_SEQ  784
#define DI     512
#define DS     16
#define DCONV  4
#define DTR    16
#define MTOT   (B_SZ * L_SEQ)   // 25088

// ---------------- scratch (static __device__, no allocation) ----------------
__device__ float g_xn  [(size_t)MTOT * CH];
__device__ float g_xz  [(size_t)MTOT * 2 * DI];
__device__ float g_xc  [(size_t)MTOT * DI];
__device__ float g_xdbl[(size_t)MTOT * 48];
__device__ float g_y   [(size_t)MTOT * DI];
__device__ float g_xbuf[(size_t)B_SZ * CH * L_SEQ];

// ============================================================================
// bf16 split helpers
// ============================================================================
__device__ __forceinline__ void bf16_split_pack(float x0, float x1,
                                                uint32_t& hi, uint32_t& lo) {
    __nv_bfloat16 h0 = __float2bfloat16(x0);
    __nv_bfloat16 h1 = __float2bfloat16(x1);
    float r0 = x0 - __bfloat162float(h0);
    float r1 = x1 - __bfloat162float(h1);
    __nv_bfloat16 l0 = __float2bfloat16(r0);
    __nv_bfloat16 l1 = __float2bfloat16(r1);
    hi = ((uint32_t)__bfloat16_as_ushort(h1) << 16) | __bfloat16_as_ushort(h0);
    lo = ((uint32_t)__bfloat16_as_ushort(l1) << 16) | __bfloat16_as_ushort(l0);
}
__device__ __forceinline__ void ldsm4(uint32_t q[4], uint32_t addr) {
    asm volatile("ldmatrix.sync.aligned.m8n8.x4.shared.b16 {%0,%1,%2,%3}, [%4];"
                 : "=r"(q[0]), "=r"(q[1]), "=r"(q[2]), "=r"(q[3]) : "r"(addr));
}
__device__ __forceinline__ void mma_bf16(float* c, const uint32_t a[4],
                                         uint32_t b0, uint32_t b1) {
    asm volatile("mma.sync.aligned.m16n8k16.row.col.f32.bf16.bf16.f32 "
                 "{%0,%1,%2,%3},{%4,%5,%6,%7},{%8,%9},{%0,%1,%2,%3};"
                 : "+f"(c[0]), "+f"(c[1]), "+f"(c[2]), "+f"(c[3])
                 : "r"(a[0]), "r"(a[1]), "r"(a[2]), "r"(a[3]), "r"(b0), "r"(b1));
}

// ============================================================================
// GEMM C[M,N] = A[M,K]*B[N,K]^T, fp32 via 3-term bf16x2 split (hh+lh+hl).
// BM=128, BN=NI*32, BK=16, 256 threads, warps 2(m) x 4(n), warp tile 64x(NI*8).
// smem planes: row-major bf16, row stride 12 u32 (48B) -> LDSM conflict-free.
// Double buffered, 1 sync per k-tile.
// ============================================================================
template<int NI, int TRANS>
__global__ void __launch_bounds__(256)
gemm_bf(const float* __restrict__ A, const float* __restrict__ Bw,
        float* __restrict__ C, int M, int N, int K) {
    constexpr int RS     = 12;            // u32 per smem row (16 bf16 + pad)
    constexpr int A_U32  = 128 * RS;      // one A plane
    constexpr int BROWS  = NI * 32;
    constexpr int B_U32  = BROWS * RS;
    constexpr int STAGE  = 2 * A_U32 + 2 * B_U32;
    constexpr int NBF    = (NI == 4) ? 8 : 4;   // B floats prefetched / thread

    extern __shared__ uint32_t smu[];
    const uint32_t sb0 = (uint32_t)__cvta_generic_to_shared(smu);

    const int tid  = threadIdx.x;
    const int bm   = blockIdx.y * 128;
    const int bn   = blockIdx.x * BROWS;
    const int warp = tid >> 5, lane = tid & 31;
    const int wm   = warp & 1, wn = warp >> 1;
    const int lm   = lane >> 3, lr = lane & 7;
    const int r    = lane >> 2, cc = lane & 3;

    const int pr = tid >> 1, ph = tid & 1;          // A producer: row, col-half
    const int br2 = tid >> 2, bq2 = tid & 3;        // B producer (NI==2)

    float acc[4][NI][4];
    #pragma unroll
    for (int i = 0; i < 4; i++)
        #pragma unroll
        for (int j = 0; j < NI; j++)
            #pragma unroll
            for (int v = 0; v < 4; v++) acc[i][j][v] = 0.0f;

    const int KT = K >> 4;
    float pA[8], pB[NBF];

    // ---- prologue global load ----
    {
        const float* pa = A + (size_t)(bm + pr) * K + ph * 8;
        float4 f0 = *reinterpret_cast<const float4*>(pa);
        float4 f1 = *reinterpret_cast<const float4*>(pa + 4);
        pA[0]=f0.x; pA[1]=f0.y; pA[2]=f0.z; pA[3]=f0.w;
        pA[4]=f1.x; pA[5]=f1.y; pA[6]=f1.z; pA[7]=f1.w;
        if (NI == 4) {
            int nb = min(bn + pr, N - 1);
            const float* pb = Bw + (size_t)nb * K + ph * 8;
            float4 g0 = *reinterpret_cast<const float4*>(pb);
            float4 g1 = *reinterpret_cast<const float4*>(pb + 4);
            pB[0]=g0.x; pB[1]=g0.y; pB[2]=g0.z; pB[3]=g0.w;
            pB[4]=g1.x; pB[5]=g1.y; pB[6]=g1.z; pB[7]=g1.w;
        } else {
            int nb = min(bn + br2, N - 1);
            float4 g0 = *reinterpret_cast<const float4*>(Bw + (size_t)nb * K + bq2 * 4);
            pB[0]=g0.x; pB[1]=g0.y; pB[2]=g0.z; pB[3]=g0.w;
        }
    }

    for (int kt = 0; kt < KT; kt++) {
        const int s = kt & 1;
        uint32_t* stg = smu + s * STAGE;

        // ---- producer: split + pack + STS ----
        {
            uint32_t h[4], l[4];
            bf16_split_pack(pA[0], pA[1], h[0], l[0]);
            bf16_split_pack(pA[2], pA[3], h[1], l[1]);
            bf16_split_pack(pA[4], pA[5], h[2], l[2]);
            bf16_split_pack(pA[6], pA[7], h[3], l[3]);
            *reinterpret_cast<uint4*>(stg + pr * RS + ph * 4) =
                make_uint4(h[0], h[1], h[2], h[3]);
            *reinterpret_cast<uint4*>(stg + A_U32 + pr * RS + ph * 4) =
                make_uint4(l[0], l[1], l[2], l[3]);
            if (NI == 4) {
                bf16_split_pack(pB[0], pB[1], h[0], l[0]);
                bf16_split_pack(pB[2], pB[3], h[1], l[1]);
                bf16_split_pack(pB[4], pB[5], h[2], l[2]);
                bf16_split_pack(pB[6], pB[7], h[3], l[3]);
                *reinterpret_cast<uint4*>(stg + 2 * A_U32 + pr * RS + ph * 4) =
                    make_uint4(h[0], h[1], h[2], h[3]);
                *reinterpret_cast<uint4*>(stg + 2 * A_U32 + B_U32 + pr * RS + ph * 4) =
                    make_uint4(l[0], l[1], l[2], l[3]);
            } else {
                bf16_split_pack(pB[0], pB[1], h[0], l[0]);
                bf16_split_pack(pB[2], pB[3], h[1], l[1]);
                *reinterpret_cast<uint2*>(stg + 2 * A_U32 + br2 * RS + bq2 * 2) =
                    make_uint2(h[0], h[1]);
                *reinterpret_cast<uint2*>(stg + 2 * A_U32 + B_U32 + br2 * RS + bq2 * 2) =
                    make_uint2(l[0], l[1]);
            }
        }

        // ---- prefetch next k-tile ----
        if (kt + 1 < KT) {
            int k0 = (kt + 1) << 4;
            const float* pa = A + (size_t)(bm + pr) * K + k0 + ph * 8;
            float4 f0 = *reinterpret_cast<const float4*>(pa);
            float4 f1 = *reinterpret_cast<const float4*>(pa + 4);
            pA[0]=f0.x; pA[1]=f0.y; pA[2]=f0.z; pA[3]=f0.w;
            pA[4]=f1.x; pA[5]=f1.y; pA[6]=f1.z; pA[7]=f1.w;
            if (NI == 4) {
                int nb = min(bn + pr, N - 1);
                const float* pb = Bw + (size_t)nb * K + k0 + ph * 8;
                float4 g0 = *reinterpret_cast<const float4*>(pb);
                float4 g1 = *reinterpret_cast<const float4*>(pb + 4);
                pB[0]=g0.x; pB[1]=g0.y; pB[2]=g0.z; pB[3]=g0.w;
                pB[4]=g1.x; pB[5]=g1.y; pB[6]=g1.z; pB[7]=g1.w;
            } else {
                int nb = min(bn + br2, N - 1);
                float4 g0 = *reinterpret_cast<const float4*>(Bw + (size_t)nb * K + k0 + bq2 * 4);
                pB[0]=g0.x; pB[1]=g0.y; pB[2]=g0.z; pB[3]=g0.w;
            }
        }

        __syncthreads();

        // ---- consumer: LDSM + 3-term bf16 mma ----
        {
            const uint32_t stb = sb0 + (uint32_t)(s * STAGE) * 4;
            uint32_t BH[NI][2], BL[NI][2];
            #pragma unroll
            for (int tt = 0; tt < NI / 2; tt++) {
                uint32_t rowb = wn * (NI * 8) + tt * 16 + (lm & 1) * 8 + lr;
                uint32_t ad = stb + (2 * A_U32) * 4 + rowb * 48 + (lm >> 1) * 16;
                uint32_t q[4];
                ldsm4(q, ad);
                BH[2*tt][0] = q[0]; BH[2*tt+1][0] = q[1];
                BH[2*tt][1] = q[2]; BH[2*tt+1][1] = q[3];
                ldsm4(q, ad + B_U32 * 4);
                BL[2*tt][0] = q[0]; BL[2*tt+1][0] = q[1];
                BL[2*tt][1] = q[2]; BL[2*tt+1][1] = q[3];
            }
            #pragma unroll
            for (int mi = 0; mi < 4; mi++) {
                uint32_t rowb = wm * 64 + mi * 16 + (lm & 1) * 8 + lr;
                uint32_t ad = stb + rowb * 48 + (lm >> 1) * 16;
                uint32_t AH[4], AL[4];
                ldsm4(AH, ad);
                ldsm4(AL, ad + A_U32 * 4);
                #pragma unroll
                for (int ni = 0; ni < NI; ni++) {
                    mma_bf16(acc[mi][ni], AH, BH[ni][0], BH[ni][1]);
                    mma_bf16(acc[mi][ni], AL, BH[ni][0], BH[ni][1]);
                    mma_bf16(acc[mi][ni], AH, BL[ni][0], BL[ni][1]);
                }
            }
        }
    }

    if (!TRANS) {
        #pragma unroll
        for (int mi = 0; mi < 4; mi++) {
            int row0 = bm + wm * 64 + mi * 16 + r;
            #pragma unroll
            for (int ni = 0; ni < NI; ni++) {
                int col = bn + wn * (NI * 8) + ni * 8 + 2 * cc;
                if (col < N) {
                    *reinterpret_cast<float2*>(C + (size_t)row0 * N + col) =
                        make_float2(acc[mi][ni][0], acc[mi][ni][1]);
                    *reinterpret_cast<float2*>(C + (size_t)(row0 + 8) * N + col) =
                        make_float2(acc[mi][ni][2], acc[mi][ni][3]);
                }
            }
        }
    } else {
        // transpose 64 n-cols at a time through smem -> coalesced (B,N,L)
        float* ct = reinterpret_cast<float*>(smu);
        __syncthreads();
        #pragma unroll
        for (int half = 0; half < 2; half++) {
            if ((wn >> 1) == half) {
                #pragma unroll
                for (int mi = 0; mi < 4; mi++) {
                    int m0 = wm * 64 + mi * 16 + r;
                    #pragma unroll
                    for (int ni = 0; ni < NI; ni++) {
                        int n0 = (wn - half * 2) * (NI * 8) + ni * 8 + 2 * cc;
                        ct[(n0    ) * 132 + m0    ] = acc[mi][ni][0];
                        ct[(n0 + 1) * 132 + m0    ] = acc[mi][ni][1];
                        ct[(n0    ) * 132 + m0 + 8] = acc[mi][ni][2];
                        ct[(n0 + 1) * 132 + m0 + 8] = acc[mi][ni][3];
                    }
                }
            }
            __syncthreads();
            for (int i = tid; i < 64 * 128; i += 256) {
                int n = i >> 7, m = i & 127;
                int row = bm + m;
                int b = row / L_SEQ;
                int l = row - b * L_SEQ;
                C[((size_t)b * N + bn + half * 64 + n) * L_SEQ + l] = ct[n * 132 + m];
            }
            __syncthreads();
        }
    }
}

// ---------------- LayerNorm, coalesced, (B,C,L) -> (B*L, C) ------------------
__global__ void ln_kernel(const float* __restrict__ x,
                          const float* __restrict__ w,
                          const float* __restrict__ bb,
                          float* __restrict__ out) {
    __shared__ float s[256][17];
    int l0 = blockIdx.x * 16;
    int b  = blockIdx.y;
    int tid = threadIdx.x;

    for (int i = tid; i < 256 * 16; i += 256) {
        int c = i >> 4, l = i & 15;
        s[c][l] = x[((size_t)b * CH + c) * L_SEQ + l0 + l];
    }
    __syncthreads();

    int l = tid >> 4, part = tid & 15;
    float a = 0.f, q = 0.f;
    #pragma unroll
    for (int j = 0; j < 16; j++) {
        float v = s[part + 16 * j][l];
        a += v;
        q = fmaf(v, v, q);
    }
    #pragma unroll
    for (int o = 1; o < 16; o <<= 1) {
        a += __shfl_xor_sync(0xffffffffu, a, o);
        q += __shfl_xor_sync(0xffffffffu, q, o);
    }
    float mu  = a * (1.0f / CH);
    float var = q * (1.0f / CH) - mu * mu;
    float inv = rsqrtf(var + 1e-5f);

    size_t base = (size_t)(b * L_SEQ + l0 + l) * CH;
    #pragma unroll
    for (int j = 0; j < 16; j++) {
        int c = part + 16 * j;
        out[base + c] = (s[c][l] - mu) * inv * w[c] + bb[c];
    }
}

// ---------------- causal depthwise conv (k=4) + SiLU, float4 ------------------
__global__ void conv_silu_kernel(const float* __restrict__ cw,
                                 const float* __restrict__ cb) {
    int idx  = blockIdx.x * 256 + threadIdx.x;   // over MTOT*DI/4
    int base = idx * 4;
    int d    = base & (DI - 1);
    int bl   = base >> 9;
    int l    = bl % L_SEQ;

    float4 acc = *reinterpret_cast<const float4*>(cb + d);
    float4 w0 = *reinterpret_cast<const float4*>(cw + (d + 0) * 4);
    float4 w1 = *reinterpret_cast<const float4*>(cw + (d + 1) * 4);
    float4 w2 = *reinterpret_cast<const float4*>(cw + (d + 2) * 4);
    float4 w3 = *reinterpret_cast<const float4*>(cw + (d + 3) * 4);
    const float wk[4][4] = {{w0.x, w1.x, w2.x, w3.x}, {w0.y, w1.y, w2.y, w3.y},
                            {w0.z, w1.z, w2.z, w3.z}, {w0.w, w1.w, w2.w, w3.w}};
    #pragma unroll
    for (int k = 0; k < DCONV; k++) {
        int ll = l - 3 + k;
        if (ll >= 0) {
            float4 v = *reinterpret_cast<const float4*>(
                g_xz + (size_t)(bl - 3 + k) * (2 * DI) + d);
            acc.x = fmaf(v.x, wk[k][0], acc.x);
            acc.y = fmaf(v.y, wk[k][1], acc.y);
            acc.z = fmaf(v.z, wk[k][2], acc.z);
            acc.w = fmaf(v.w, wk[k][3], acc.w);
        }
    }
    acc.x = acc.x / (1.0f + __expf(-acc.x));
    acc.y = acc.y / (1.0f + __expf(-acc.y));
    acc.z = acc.z / (1.0f + __expf(-acc.z));
    acc.w = acc.w / (1.0f + __expf(-acc.w));
    *reinterpret_cast<float4*>(g_xc + base) = acc;
}

// ---------------- selective scan with fused dt_proj+softplus ------------------
// 2 threads per (b,d), 8 states each; dt computed from smem dt_r and
// register-resident dt_proj weights.
__global__ void scan_kernel(const float* __restrict__ A_log,
                            const float* __restrict__ Dp,
                            const float* __restrict__ dtw,
                            const float* __restrict__ dtb) {
    int b    = blockIdx.x;
    int tid  = threadIdx.x;                 // 128
    int dl   = tid >> 1, half = tid & 1;
    int d    = blockIdx.y * 64 + dl;

    float w[DTR];
    #pragma unroll
    for (int i = 0; i < DTR; i++) w[i] = dtw[d * DTR + i];
    float bias = dtb[d];

    float a[8];
    bool powok = true;
    #pragma unroll
    for (int s = 0; s < 8; s++) {
        a[s] = -__expf(A_log[d * DS + half * 8 + s]);
        float kf = (float)(half * 8 + s + 1);
        powok = powok && (fabsf(-a[s] - kf) < 1e-3f * kf);
    }
    float Dd = Dp[d];

    float h[8];
    #pragma unroll
    for (int s = 0; s < 8; s++) h[s] = 0.0f;

    __shared__ float sBC[16][48];

    for (int c0 = 0; c0 < L_SEQ; c0 += 16) {
        __syncthreads();
        for (int i = tid; i < 16 * 48; i += 128) {
            int st = i / 48, j = i - st * 48;
            sBC[st][j] = g_xdbl[((size_t)b * L_SEQ + c0 + st) * 48 + j];
        }
        __syncthreads();
        #pragma unroll 4
        for (int st = 0; st < 16; st++) {
            size_t row = (size_t)b * L_SEQ + c0 + st;
            float dtl = bias;
            #pragma unroll
            for (int i = 0; i < DTR; i++) dtl = fmaf(w[i], sBC[st][i], dtl);
            float dtv = (dtl > 20.0f) ? dtl : log1pf(__expf(dtl));
            float xv  = g_xc[row * DI + d];
            float dtx = dtv * xv;
            float dA[8];
            if (powok) {
                float rr = __expf(-dtv);
                float r2 = rr * rr, r4 = r2 * r2, r8v = r4 * r4;
                float p = half ? r8v : 1.0f;
                #pragma unroll
                for (int s = 0; s < 8; s++) { p *= rr; dA[s] = p; }
            } else {
                #pragma unroll
                for (int s = 0; s < 8; s++) dA[s] = __expf(dtv * a[s]);
            }
            float yacc = 0.0f;
            #pragma unroll
            for (int s = 0; s < 8; s++) {
                h[s] = fmaf(h[s], dA[s], dtx * sBC[st][16 + half * 8 + s]);
                yacc = fmaf(h[s], sBC[st][32 + half * 8 + s], yacc);
            }
            yacc += __shfl_xor_sync(0xffffffffu, yacc, 1);
            if (half == 0) {
                float zv = g_xz[row * 2 * DI + DI + d];
                float yf = fmaf(xv, Dd, yacc) * (zv / (1.0f + __expf(-zv)));
                g_y[row * DI + d] = yf;
            }
        }
    }
}

// ------------------------------- launcher -------------------------------------
extern "C" void kernel_launch(void* const* d_in, const int* in_sizes, int n_in,
                              void* d_out, int out_size) {
    const float* bbox   = (const float*)d_in[0];
    const float* norm_w = (const float*)d_in[1];
    const float* norm_b = (const float*)d_in[2];
    const float* in_w   = (const float*)d_in[3];
    const float* conv_w = (const float*)d_in[4];
    const float* conv_b = (const float*)d_in[5];
    const float* xp_w   = (const float*)d_in[6];
    const float* dtp_w  = (const float*)d_in[7];
    const float* dtp_b  = (const float*)d_in[8];
    const float* A_log  = (const float*)d_in[9];
    const float* Dp     = (const float*)d_in[10];
    const float* out_w  = (const float*)d_in[11];
    float* out = (float*)d_out;

    // smem: NI4 = 49152 B, NI2 = 36864 B
    cudaFuncSetAttribute(gemm_bf<4,0>, cudaFuncAttributeMaxDynamicSharedMemorySize, 49152);
    cudaFuncSetAttribute(gemm_bf<4,1>, cudaFuncAttributeMaxDynamicSharedMemorySize, 49152);
    cudaFuncSetAttribute(gemm_bf<2,0>, cudaFuncAttributeMaxDynamicSharedMemorySize, 36864);

    float *xn, *xz, *xc, *xdbl, *yy, *xbuf;
    cudaGetSymbolAddress((void**)&xn,   g_xn);
    cudaGetSymbolAddress((void**)&xz,   g_xz);
    cudaGetSymbolAddress((void**)&xc,   g_xc);
    cudaGetSymbolAddress((void**)&xdbl, g_xdbl);
    cudaGetSymbolAddress((void**)&yy,   g_y);
    cudaGetSymbolAddress((void**)&xbuf, g_xbuf);

    for (int i = 0; i < 2; i++) {
        const float* xin = (i == 0) ? bbox : xbuf;
        float* xout      = (i == 0) ? xbuf : out;

        {   // layernorm
            dim3 g(49, 32);
            ln_kernel<<<g, 256>>>(xin, norm_w + i * CH, norm_b + i * CH, xn);
        }
        {   // in_proj: (25088,256)x(1024,256)^T
            dim3 g(1024 / 128, MTOT / 128);
            gemm_bf<4,0><<<g, 256, 49152>>>(xn, in_w + (size_t)i * 2 * DI * CH, xz,
                                            MTOT, 2 * DI, CH);
        }
        // conv + silu (float4)
        conv_silu_kernel<<<(MTOT * DI / 4) / 256, 256>>>(conv_w + i * DI * DCONV,
                                                         conv_b + i * DI);
        {   // x_proj: (25088,512)x(48,512)^T
            dim3 g(1, MTOT / 128);
            gemm_bf<2,0><<<g, 256, 36864>>>(xc, xp_w + (size_t)i * 48 * DI, xdbl,
                                            MTOT, 48, DI);
        }
        {   // selective scan (dt_proj fused)
            dim3 g(B_SZ, DI / 64);
            scan_kernel<<<g, 128>>>(A_log + i * DI * DS, Dp + i * DI,
                                    dtp_w + (size_t)i * DI * DTR, dtp_b + i * DI);
        }
        {   // out_proj: (25088,512)x(256,512)^T -> (B,256,L)
            dim3 g(256 / 128, MTOT / 128);
            gemm_bf<4,1><<<g, 256, 49152>>>(yy, out_w + (size_t)i * CH * DI, xout,
                                            MTOT, CH, DI);
        }
    }
}